// round 2
// baseline (speedup 1.0000x reference)
#include <cuda_runtime.h>
#include <math.h>
#include <stdint.h>

#define BB 4
#define CC 256
#define LL 2304        // 48*48
#define NHH 8
#define DKK 64
#define DD 512         // NHH*DKK
#define BN_EPS 1e-5f
#define NEG_SLOPE 0.01f

// ---------------- scratch (allocation-free: __device__ globals) ----------------
__device__ float g_q[(size_t)BB * DD * LL];
__device__ float g_k[(size_t)BB * DD * LL];
__device__ float g_v[(size_t)BB * DD * LL];
__device__ float g_attn[(size_t)BB * DD * LL];
__device__ float g_proj[(size_t)BB * CC * LL];
__device__ float g_mean[CC];
__device__ float g_rstd[CC];

// ---------------------------------------------------------------------------
// Generic W*X GEMM:  Out[b][m][n] = sum_k W[m*K+k] * In[b][k][n]
// Tiles: 64x64 output, 16 k-step. 256 threads, each computes 4x4.
// Requires M%64==0, N%64==0, K%16==0 (all true here).
// ---------------------------------------------------------------------------
__global__ void gemm_wx(const float* __restrict__ W, const float* __restrict__ In,
                        float* __restrict__ Out, int M, int K, int N) {
    __shared__ float Ws[16][64];   // [k][m]
    __shared__ float Is[16][64];   // [k][n]

    const int b  = blockIdx.z;
    const float* in  = In  + (size_t)b * K * N;
    float*       out = Out + (size_t)b * M * N;
    const int m0 = blockIdx.y * 64;
    const int n0 = blockIdx.x * 64;
    const int tid = threadIdx.x;
    const int ty = tid >> 4;       // 0..15
    const int tx = tid & 15;       // 0..15

    float acc[4][4] = {};

    for (int k0 = 0; k0 < K; k0 += 16) {
        // Is: 16 rows x 16 float4; one float4 per thread, coalesced
        {
            int r = tid >> 4, v = tid & 15;
            float4 t = *(const float4*)(in + (size_t)(k0 + r) * N + n0 + v * 4);
            *(float4*)&Is[r][v * 4] = t;
        }
        // Ws: read W[m][k] as float4 along k, store transposed [k][m]
        {
            int mm = tid >> 2, kg = tid & 3;
            float4 t = *(const float4*)(W + (size_t)(m0 + mm) * K + k0 + kg * 4);
            Ws[kg * 4 + 0][mm] = t.x;
            Ws[kg * 4 + 1][mm] = t.y;
            Ws[kg * 4 + 2][mm] = t.z;
            Ws[kg * 4 + 3][mm] = t.w;
        }
        __syncthreads();

        #pragma unroll
        for (int kk = 0; kk < 16; kk++) {
            float wv[4], iv[4];
            #pragma unroll
            for (int i = 0; i < 4; i++) wv[i] = Ws[kk][ty * 4 + i];
            #pragma unroll
            for (int j = 0; j < 4; j++) iv[j] = Is[kk][tx * 4 + j];
            #pragma unroll
            for (int i = 0; i < 4; i++)
                #pragma unroll
                for (int j = 0; j < 4; j++)
                    acc[i][j] += wv[i] * iv[j];
        }
        __syncthreads();
    }

    #pragma unroll
    for (int i = 0; i < 4; i++)
        #pragma unroll
        for (int j = 0; j < 4; j++)
            out[(size_t)(m0 + ty * 4 + i) * N + n0 + tx * 4 + j] = acc[i][j];
}

// ---------------------------------------------------------------------------
// Fused flash-style attention. Q/K/V in [bh][d][l] layout (d-major).
// Block = 64 queries of one (b,h). Streams 64-key tiles, online softmax.
// Writes g_attn[bh*DK + d][l=q].
// ---------------------------------------------------------------------------
struct AttnSmem {
    float Qs[DKK][64];   // [d][q], pre-scaled by 1/8
    float Ks[DKK][64];   // [d][k]
    float Vs[64][DKK];   // [k][d]  (transposed for conflict-free PV)
    float Ps[64][68];    // [q][k], padded stride
    float m[64];
    float l[64];
    float scale[64];
};

__global__ void attn_kernel() {
    extern __shared__ char smem_raw[];
    AttnSmem* S = (AttnSmem*)smem_raw;

    const int bh = blockIdx.y;             // b*NH + h
    const int q0 = blockIdx.x * 64;
    const float* Qp = g_q + (size_t)bh * DKK * LL;
    const float* Kp = g_k + (size_t)bh * DKK * LL;
    const float* Vp = g_v + (size_t)bh * DKK * LL;

    const int tid = threadIdx.x;
    const int ty = tid >> 4, tx = tid & 15;

    // Load Q tile [64 d][64 q], scaled by 1/sqrt(DK)=0.125
    #pragma unroll
    for (int i = 0; i < 4; i++) {
        int d = i * 16 + (tid >> 4);
        int v = tid & 15;
        float4 t = *(const float4*)(Qp + (size_t)d * LL + q0 + v * 4);
        t.x *= 0.125f; t.y *= 0.125f; t.z *= 0.125f; t.w *= 0.125f;
        *(float4*)&S->Qs[d][v * 4] = t;
    }
    if (tid < 64) { S->m[tid] = -1e30f; S->l[tid] = 0.0f; }

    float o[4][4] = {};   // [qi][di]

    for (int k0 = 0; k0 < LL; k0 += 64) {
        __syncthreads();   // previous iteration fully consumed Ks/Vs/Ps

        // Load K tile [d][k] and V tile transposed [k][d]
        #pragma unroll
        for (int i = 0; i < 4; i++) {
            int d = i * 16 + (tid >> 4);
            int v = tid & 15;
            *(float4*)&S->Ks[d][v * 4] =
                *(const float4*)(Kp + (size_t)d * LL + k0 + v * 4);
            float4 t = *(const float4*)(Vp + (size_t)d * LL + k0 + v * 4);
            S->Vs[v * 4 + 0][d] = t.x;
            S->Vs[v * 4 + 1][d] = t.y;
            S->Vs[v * 4 + 2][d] = t.z;
            S->Vs[v * 4 + 3][d] = t.w;
        }
        __syncthreads();

        // Logits: s[qi][ki] = sum_d Qs[d][q] * Ks[d][k]
        float s[4][4] = {};
        #pragma unroll
        for (int d = 0; d < DKK; d++) {
            float qv[4], kv[4];
            #pragma unroll
            for (int i = 0; i < 4; i++) qv[i] = S->Qs[d][ty * 4 + i];
            #pragma unroll
            for (int j = 0; j < 4; j++) kv[j] = S->Ks[d][tx * 4 + j];
            #pragma unroll
            for (int i = 0; i < 4; i++)
                #pragma unroll
                for (int j = 0; j < 4; j++)
                    s[i][j] += qv[i] * kv[j];
        }
        #pragma unroll
        for (int i = 0; i < 4; i++)
            #pragma unroll
            for (int j = 0; j < 4; j++)
                S->Ps[ty * 4 + i][tx * 4 + j] = s[i][j];
        __syncthreads();

        // Row max + rescale factor (threads 0..63, one row each)
        if (tid < 64) {
            float mo = S->m[tid];
            float mn = mo;
            #pragma unroll 8
            for (int k = 0; k < 64; k++) mn = fmaxf(mn, S->Ps[tid][k]);
            float sc = __expf(mo - mn);
            S->scale[tid] = sc;
            S->m[tid] = mn;
            S->l[tid] *= sc;
        }
        __syncthreads();

        // Exponentiate in place
        #pragma unroll
        for (int i = 0; i < 4; i++) {
            float mm = S->m[ty * 4 + i];
            #pragma unroll
            for (int j = 0; j < 4; j++)
                S->Ps[ty * 4 + i][tx * 4 + j] =
                    __expf(S->Ps[ty * 4 + i][tx * 4 + j] - mm);
        }
        __syncthreads();

        // Row sums (readers only; concurrent with PV reads below is fine,
        // but keep ordering simple: do sums first inside the same phase)
        if (tid < 64) {
            float sum = 0.0f;
            #pragma unroll 8
            for (int k = 0; k < 64; k++) sum += S->Ps[tid][k];
            S->l[tid] += sum;
        }

        // Rescale accumulators, then PV: o[qi][di] += P[q][k] * V[k][d]
        #pragma unroll
        for (int i = 0; i < 4; i++) {
            float sc = S->scale[ty * 4 + i];
            #pragma unroll
            for (int j = 0; j < 4; j++) o[i][j] *= sc;
        }
        #pragma unroll
        for (int k = 0; k < 64; k++) {
            float pv[4], vv[4];
            #pragma unroll
            for (int i = 0; i < 4; i++) pv[i] = S->Ps[ty * 4 + i][k];
            #pragma unroll
            for (int j = 0; j < 4; j++) vv[j] = S->Vs[k][tx * 4 + j];
            #pragma unroll
            for (int i = 0; i < 4; i++)
                #pragma unroll
                for (int j = 0; j < 4; j++)
                    o[i][j] += pv[i] * vv[j];
        }
    }
    __syncthreads();

    // Normalize and write out in [d][l] layout for the Wo GEMM
    float* Op = g_attn + (size_t)bh * DKK * LL;
    #pragma unroll
    for (int i = 0; i < 4; i++) {
        float inv = 1.0f / S->l[ty * 4 + i];
        #pragma unroll
        for (int j = 0; j < 4; j++)
            Op[(size_t)(tx * 4 + j) * LL + q0 + ty * 4 + i] = o[i][j] * inv;
    }
}

// ---------------------------------------------------------------------------
// BatchNorm statistics: one block per channel, reduce over (b, l)
// ---------------------------------------------------------------------------
__global__ void bn_stats() {
    const int c = blockIdx.x;
    float sum = 0.0f, sumsq = 0.0f;
    for (int b = 0; b < BB; b++) {
        const float* p = g_proj + ((size_t)b * CC + c) * LL;
        for (int i = threadIdx.x; i < LL; i += blockDim.x) {
            float v = p[i];
            sum += v;
            sumsq += v * v;
        }
    }
    __shared__ float ss[256], sq[256];
    ss[threadIdx.x] = sum;
    sq[threadIdx.x] = sumsq;
    __syncthreads();
    for (int off = 128; off > 0; off >>= 1) {
        if (threadIdx.x < off) {
            ss[threadIdx.x] += ss[threadIdx.x + off];
            sq[threadIdx.x] += sq[threadIdx.x + off];
        }
        __syncthreads();
    }
    if (threadIdx.x == 0) {
        const float inv_n = 1.0f / (float)(BB * LL);
        float mean = ss[0] * inv_n;
        float var  = sq[0] * inv_n - mean * mean;
        g_mean[c] = mean;
        g_rstd[c] = rsqrtf(var + BN_EPS);
    }
}

// ---------------------------------------------------------------------------
// BN apply + gamma-scale + residual + LeakyReLU (float4 vectorized)
// ---------------------------------------------------------------------------
__global__ void bn_apply(const float* __restrict__ x,
                         const float* __restrict__ bn_w,
                         const float* __restrict__ bn_b,
                         const float* __restrict__ gamma,
                         float* __restrict__ out) {
    const size_t i4 = (size_t)blockIdx.x * blockDim.x + threadIdx.x;
    const size_t n4 = (size_t)BB * CC * LL / 4;
    if (i4 >= n4) return;
    const int c = (int)((i4 / (LL / 4)) % CC);
    const float mean = g_mean[c];
    const float rstd = g_rstd[c];
    const float w = bn_w[c] * rstd;
    const float bcon = bn_b[c] - mean * w;
    const float g = gamma[0];

    float4 v = ((const float4*)g_proj)[i4];
    float4 xr = ((const float4*)x)[i4];
    float4 y;
    y.x = g * (v.x * w + bcon) + xr.x;
    y.y = g * (v.y * w + bcon) + xr.y;
    y.z = g * (v.z * w + bcon) + xr.z;
    y.w = g * (v.w * w + bcon) + xr.w;
    y.x = y.x >= 0.0f ? y.x : NEG_SLOPE * y.x;
    y.y = y.y >= 0.0f ? y.y : NEG_SLOPE * y.y;
    y.z = y.z >= 0.0f ? y.z : NEG_SLOPE * y.z;
    y.w = y.w >= 0.0f ? y.w : NEG_SLOPE * y.w;
    ((float4*)out)[i4] = y;
}

// ---------------------------------------------------------------------------
extern "C" void kernel_launch(void* const* d_in, const int* in_sizes, int n_in,
                              void* d_out, int out_size) {
    const float* x     = (const float*)d_in[0];
    const float* Wq    = (const float*)d_in[1];
    const float* Wk    = (const float*)d_in[2];
    const float* Wv    = (const float*)d_in[3];
    const float* Wo    = (const float*)d_in[4];
    const float* bn_w  = (const float*)d_in[5];
    const float* bn_b  = (const float*)d_in[6];
    const float* gamma = (const float*)d_in[7];
    float* out = (float*)d_out;

    float *gq, *gk, *gv, *gattn, *gproj;
    cudaGetSymbolAddress((void**)&gq,    g_q);
    cudaGetSymbolAddress((void**)&gk,    g_k);
    cudaGetSymbolAddress((void**)&gv,    g_v);
    cudaGetSymbolAddress((void**)&gattn, g_attn);
    cudaGetSymbolAddress((void**)&gproj, g_proj);

    static bool attr_set = false;
    if (!attr_set) {
        cudaFuncSetAttribute(attn_kernel,
                             cudaFuncAttributeMaxDynamicSharedMemorySize,
                             (int)sizeof(AttnSmem));
        attr_set = true;
    }

    // Q/K/V projections: [512x256] x [256x2304] per batch
    dim3 gproj_grid(LL / 64, DD / 64, BB);
    gemm_wx<<<gproj_grid, 256>>>(Wq, x, gq, DD, CC, LL);
    gemm_wx<<<gproj_grid, 256>>>(Wk, x, gk, DD, CC, LL);
    gemm_wx<<<gproj_grid, 256>>>(Wv, x, gv, DD, CC, LL);

    // Fused attention: 36 q-tiles x 32 (b,h)
    attn_kernel<<<dim3(LL / 64, BB * NHH), 256, sizeof(AttnSmem)>>>();

    // Output projection: [256x512] x [512x2304] per batch
    gemm_wx<<<dim3(LL / 64, CC / 64, BB), 256>>>(Wo, gattn, gproj, CC, DD, LL);

    // BatchNorm stats + fused epilogue
    bn_stats<<<CC, 256>>>();
    const int n4 = BB * CC * LL / 4;
    bn_apply<<<(n4 + 255) / 256, 256>>>(x, bn_w, bn_b, gamma, out);
}

// round 5
// speedup vs baseline: 7.0731x; 7.0731x over previous
#include <cuda_runtime.h>
#include <cuda_fp16.h>
#include <math.h>
#include <stdint.h>

#define BB 4
#define CC 256
#define LL 2304
#define NHH 8
#define DKK 64
#define DD 512
#define BHT 32
#define BN_EPS 1e-5f
#define NEG_SLOPE 0.01f
#define QSCALE 0.18033688011112042f   // (1/sqrt(64)) * log2(e)

// ------------------------- scratch -------------------------
__device__ __half g_xt  [(size_t)BB*LL*CC];
__device__ __half g_wqkv[1536*CC];
__device__ __half g_wo16[CC*DD];
__device__ __half g_qb  [(size_t)BHT*LL*DKK];
__device__ __half g_kb  [(size_t)BHT*LL*DKK];
__device__ __half g_vb  [(size_t)BHT*LL*DKK];
__device__ __half g_vt  [(size_t)BHT*DKK*LL];
__device__ __half g_ob  [(size_t)BB*LL*DD];
__device__ float  g_proj[(size_t)BB*CC*LL];
__device__ float  g_mean[CC];
__device__ float  g_rstd[CC];

// ------------------------- helpers -------------------------
__device__ __forceinline__ float ex2f(float x) {
    float y; asm("ex2.approx.ftz.f32 %0, %1;" : "=f"(y) : "f"(x)); return y;
}
__device__ __forceinline__ void mma16816(float* c, const uint32_t* a, const uint32_t* b) {
    asm volatile("mma.sync.aligned.m16n8k16.row.col.f32.f16.f16.f32 "
        "{%0,%1,%2,%3}, {%4,%5,%6,%7}, {%8,%9}, {%0,%1,%2,%3};"
        : "+f"(c[0]), "+f"(c[1]), "+f"(c[2]), "+f"(c[3])
        : "r"(a[0]), "r"(a[1]), "r"(a[2]), "r"(a[3]), "r"(b[0]), "r"(b[1]));
}
__device__ __forceinline__ uint32_t packh2(float x, float y) {
    __half2 h = __halves2half2(__float2half(x), __float2half(y));
    return *(uint32_t*)&h;
}

// ------------------------- prep kernels -------------------------
__global__ void cvt_f2h(__half* dst, const float* __restrict__ src, int n) {
    int i = blockIdx.x * blockDim.x + threadIdx.x;
    if (i < n) dst[i] = __float2half(src[i]);
}

__global__ void xpose(const float* __restrict__ x) {   // x[b][c][l] -> g_xt[b][l][c] fp16
    __shared__ float t[32][33];
    int b = blockIdx.z, c0 = blockIdx.y * 32, l0 = blockIdx.x * 32;
    int tx = threadIdx.x, ty = threadIdx.y;
    #pragma unroll
    for (int k = 0; k < 4; k++)
        t[ty + k*8][tx] = x[((size_t)b*CC + c0 + ty + k*8)*LL + l0 + tx];
    __syncthreads();
    #pragma unroll
    for (int k = 0; k < 4; k++)
        g_xt[((size_t)b*LL + l0 + ty + k*8)*CC + c0 + tx] = __float2half(t[tx][ty + k*8]);
}

__global__ void vtrans() {   // g_vb[bh][l][dk] -> g_vt[bh][dk][l]
    __shared__ __half t[32][33];
    int bh = blockIdx.z, d0 = blockIdx.y * 32, l0 = blockIdx.x * 32;
    int tx = threadIdx.x, ty = threadIdx.y;
    #pragma unroll
    for (int k = 0; k < 4; k++)
        t[ty + k*8][tx] = g_vb[((size_t)bh*LL + l0 + ty + k*8)*DKK + d0 + tx];
    __syncthreads();
    #pragma unroll
    for (int k = 0; k < 4; k++)
        g_vt[((size_t)bh*DKK + d0 + ty + k*8)*LL + l0 + tx] = t[tx][ty + k*8];
}

// ------------------------- mma GEMM -------------------------
// D[m0..+127][n0..+127] = sum_k A[m][k]*B[n][k], fp16 K-major, fp32 accum.
// 8 warps: warp grid 4(m)x2(n), warp tile 32x64.
// MODE 0: scatter Q/K/V fp16. MODE 1: transposed fp32 store to g_proj.
#define ASTR 72
template<int KH, int MODE>
__global__ void __launch_bounds__(256) gemm_mma(const __half* __restrict__ Ag,
                                               const __half* __restrict__ Bg) {
    __shared__ char smem_raw[2 * 128 * ASTR * 2];   // 36864 B
    __half* As = (__half*)smem_raw;
    __half* Bs = As + 128 * ASTR;

    const int tid = threadIdx.x;
    const int lane = tid & 31, wid = tid >> 5;
    const int wm = wid >> 1, wn = wid & 1;          // 4 x 2
    const int m0 = blockIdx.y * 128, n0 = blockIdx.x * 128;
    const int gr = lane >> 2, gc = lane & 3;        // groupID, tig

    float acc[2][8][4];
    #pragma unroll
    for (int i = 0; i < 2; i++)
        #pragma unroll
        for (int j = 0; j < 8; j++)
            #pragma unroll
            for (int u = 0; u < 4; u++) acc[i][j][u] = 0.f;

    for (int kc = 0; kc < KH; kc += 64) {
        __syncthreads();
        #pragma unroll
        for (int t = 0; t < 4; t++) {               // 128 rows x 8 int4
            int i = tid + t*256, r = i >> 3, c = i & 7;
            *(int4*)(As + r*ASTR + c*8) = *(const int4*)(Ag + (size_t)(m0+r)*KH + kc + c*8);
            *(int4*)(Bs + r*ASTR + c*8) = *(const int4*)(Bg + (size_t)(n0+r)*KH + kc + c*8);
        }
        __syncthreads();
        #pragma unroll
        for (int kk = 0; kk < 64; kk += 16) {
            uint32_t a[2][4], b[8][2];
            #pragma unroll
            for (int mt = 0; mt < 2; mt++) {
                const __half* p = As + (wm*32 + mt*16 + gr)*ASTR + kk + 2*gc;
                a[mt][0] = *(const uint32_t*)p;
                a[mt][1] = *(const uint32_t*)(p + 8*ASTR);
                a[mt][2] = *(const uint32_t*)(p + 8);
                a[mt][3] = *(const uint32_t*)(p + 8*ASTR + 8);
            }
            #pragma unroll
            for (int nt = 0; nt < 8; nt++) {
                const __half* p = Bs + (wn*64 + nt*8 + gr)*ASTR + kk + 2*gc;
                b[nt][0] = *(const uint32_t*)p;
                b[nt][1] = *(const uint32_t*)(p + 8);
            }
            #pragma unroll
            for (int mt = 0; mt < 2; mt++)
                #pragma unroll
                for (int nt = 0; nt < 8; nt++)
                    mma16816(acc[mt][nt], a[mt], b[nt]);
        }
    }

    if (MODE == 0) {
        const int b = m0 / LL, lbase = m0 % LL;
        #pragma unroll
        for (int mt = 0; mt < 2; mt++)
            #pragma unroll
            for (int half = 0; half < 2; half++) {
                int l = lbase + wm*32 + mt*16 + gr + half*8;
                #pragma unroll
                for (int nt = 0; nt < 8; nt++) {
                    int n = n0 + wn*64 + nt*8 + 2*gc;
                    int which = n >> 9, h = (n & 511) >> 6, dk = n & 63;
                    __half* dst = (which == 0) ? g_qb : (which == 1) ? g_kb : g_vb;
                    float sc = (which == 0) ? QSCALE : 1.0f;
                    uint32_t v = packh2(acc[mt][nt][half*2] * sc, acc[mt][nt][half*2+1] * sc);
                    *(uint32_t*)(dst + ((size_t)(b*NHH + h)*LL + l)*DKK + dk) = v;
                }
            }
    } else {
        float* stage = (float*)smem_raw;            // [64][132] floats = 33792 B
        const int b = m0 / LL, l0 = m0 % LL;
        #pragma unroll
        for (int p = 0; p < 2; p++) {
            __syncthreads();
            if (wn == p) {
                #pragma unroll
                for (int mt = 0; mt < 2; mt++)
                    #pragma unroll
                    for (int nt = 0; nt < 8; nt++)
                        #pragma unroll
                        for (int u = 0; u < 4; u++) {
                            int row = wm*32 + mt*16 + gr + (u >> 1)*8;
                            int col = nt*8 + 2*gc + (u & 1);
                            stage[col*132 + row] = acc[mt][nt][u];
                        }
            }
            __syncthreads();
            #pragma unroll
            for (int k = 0; k < 8; k++) {
                int idx = tid + k*256;               // 2048 float4
                int nl = idx >> 5, mw = idx & 31;
                *(float4*)(g_proj + ((size_t)b*CC + n0 + p*64 + nl)*LL + l0 + mw*4) =
                    *(const float4*)(stage + nl*132 + mw*4);
            }
        }
    }
}

// ------------------------- fused flash attention -------------------------
#define VSTR 136
#define SM_Q 0
#define SM_K (128*ASTR)
#define SM_V (2*128*ASTR)
#define ATTN_SMEM ((2*128*ASTR + 64*VSTR) * 2)

__global__ void __launch_bounds__(256, 1) attn_mma() {
    extern __shared__ __half sh[];
    __half* Qs = sh + SM_Q;
    __half* Ks = sh + SM_K;
    __half* Vs = sh + SM_V;

    const int tid = threadIdx.x;
    const int lane = tid & 31, wid = tid >> 5;
    const int gr = lane >> 2, gc = lane & 3;
    const int bh = blockIdx.y, q0 = blockIdx.x * 128;
    const __half* Qp = g_qb + (size_t)bh*LL*DKK;
    const __half* Kp = g_kb + (size_t)bh*LL*DKK;
    const __half* Vp = g_vt + (size_t)bh*DKK*LL;

    // Q tile -> smem (128 rows x 64 halves)
    #pragma unroll
    for (int t = 0; t < 4; t++) {
        int i = tid + t*256, r = i >> 3, c = i & 7;
        *(int4*)(Qs + r*ASTR + c*8) = *(const int4*)(Qp + (size_t)(q0+r)*DKK + c*8);
    }
    __syncthreads();

    // Q fragments: warp owns rows wid*16..+15, full k=64 (4 k16 steps)
    uint32_t aq[4][4];
    #pragma unroll
    for (int kk = 0; kk < 4; kk++) {
        const __half* p = Qs + (wid*16 + gr)*ASTR + kk*16 + 2*gc;
        aq[kk][0] = *(const uint32_t*)p;
        aq[kk][1] = *(const uint32_t*)(p + 8*ASTR);
        aq[kk][2] = *(const uint32_t*)(p + 8);
        aq[kk][3] = *(const uint32_t*)(p + 8*ASTR + 8);
    }

    float o[8][4];
    #pragma unroll
    for (int j = 0; j < 8; j++)
        #pragma unroll
        for (int u = 0; u < 4; u++) o[j][u] = 0.f;
    float m2[2] = {-1e30f, -1e30f}, l2[2] = {0.f, 0.f};

    for (int kt = 0; kt < LL/128; kt++) {
        const int k0 = kt * 128;
        __syncthreads();
        #pragma unroll
        for (int t = 0; t < 4; t++) {               // K tile 128x64
            int i = tid + t*256, r = i >> 3, c = i & 7;
            *(int4*)(Ks + r*ASTR + c*8) = *(const int4*)(Kp + (size_t)(k0+r)*DKK + c*8);
        }
        #pragma unroll
        for (int t = 0; t < 4; t++) {               // Vt tile 64x128
            int i = tid + t*256, r = i >> 4, c = i & 15;
            *(int4*)(Vs + r*VSTR + c*8) = *(const int4*)(Vp + (size_t)r*LL + k0 + c*8);
        }
        __syncthreads();

        // S = Q Kt : warp computes 16 q-rows x 128 k-cols (16 n-tiles)
        float s[16][4];
        #pragma unroll
        for (int j = 0; j < 16; j++)
            #pragma unroll
            for (int u = 0; u < 4; u++) s[j][u] = 0.f;
        #pragma unroll
        for (int kk = 0; kk < 4; kk++) {
            #pragma unroll
            for (int nt = 0; nt < 16; nt++) {
                uint32_t b[2];
                const __half* p = Ks + (nt*8 + gr)*ASTR + kk*16 + 2*gc;
                b[0] = *(const uint32_t*)p;
                b[1] = *(const uint32_t*)(p + 8);
                mma16816(s[nt], aq[kk], b);
            }
        }

        // online softmax: thread owns rows gr (u=0,1) and gr+8 (u=2,3)
        float sc[2];
        #pragma unroll
        for (int hf = 0; hf < 2; hf++) {
            float mx = -1e30f;
            #pragma unroll
            for (int nt = 0; nt < 16; nt++)
                mx = fmaxf(mx, fmaxf(s[nt][hf*2], s[nt][hf*2+1]));
            mx = fmaxf(mx, __shfl_xor_sync(0xffffffff, mx, 1));
            mx = fmaxf(mx, __shfl_xor_sync(0xffffffff, mx, 2));
            float mn = fmaxf(m2[hf], mx);
            sc[hf] = ex2f(m2[hf] - mn);
            float ls = 0.f;
            #pragma unroll
            for (int nt = 0; nt < 16; nt++) {
                s[nt][hf*2]   = ex2f(s[nt][hf*2]   - mn);
                s[nt][hf*2+1] = ex2f(s[nt][hf*2+1] - mn);
                ls += s[nt][hf*2] + s[nt][hf*2+1];
            }
            ls += __shfl_xor_sync(0xffffffff, ls, 1);
            ls += __shfl_xor_sync(0xffffffff, ls, 2);
            l2[hf] = l2[hf] * sc[hf] + ls;
            m2[hf] = mn;
        }
        #pragma unroll
        for (int j = 0; j < 8; j++) {
            o[j][0] *= sc[0]; o[j][1] *= sc[0];
            o[j][2] *= sc[1]; o[j][3] *= sc[1];
        }

        // P fragments (D-layout == A-layout) : 8 k16 steps over 128 keys
        #pragma unroll
        for (int kk = 0; kk < 8; kk++) {
            uint32_t ap[4];
            ap[0] = packh2(s[2*kk][0],   s[2*kk][1]);
            ap[1] = packh2(s[2*kk][2],   s[2*kk][3]);
            ap[2] = packh2(s[2*kk+1][0], s[2*kk+1][1]);
            ap[3] = packh2(s[2*kk+1][2], s[2*kk+1][3]);
            #pragma unroll
            for (int nt = 0; nt < 8; nt++) {
                uint32_t b[2];
                const __half* p = Vs + (nt*8 + gr)*VSTR + kk*16 + 2*gc;
                b[0] = *(const uint32_t*)p;
                b[1] = *(const uint32_t*)(p + 8);
                mma16816(o[nt], ap, b);
            }
        }
    }

    // normalize + store: g_ob[b][l][h*64+d]
    const int b = bh >> 3, h = bh & 7;
    float inv0 = 1.0f / l2[0], inv1 = 1.0f / l2[1];
    #pragma unroll
    for (int hf = 0; hf < 2; hf++) {
        int l = q0 + wid*16 + gr + hf*8;
        float inv = hf ? inv1 : inv0;
        __half* dst = g_ob + ((size_t)b*LL + l)*DD + h*DKK;
        #pragma unroll
        for (int nt = 0; nt < 8; nt++)
            *(uint32_t*)(dst + nt*8 + 2*gc) = packh2(o[nt][hf*2]*inv, o[nt][hf*2+1]*inv);
    }
}

// ------------------------- BN -------------------------
__global__ void bn_stats() {
    const int c = blockIdx.x;
    float sum = 0.f, sumsq = 0.f;
    for (int b = 0; b < BB; b++) {
        const float* p = g_proj + ((size_t)b*CC + c)*LL;
        for (int i = threadIdx.x; i < LL; i += blockDim.x) {
            float v = p[i]; sum += v; sumsq += v*v;
        }
    }
    __shared__ float ss[256], sq[256];
    ss[threadIdx.x] = sum; sq[threadIdx.x] = sumsq;
    __syncthreads();
    for (int off = 128; off > 0; off >>= 1) {
        if (threadIdx.x < off) { ss[threadIdx.x] += ss[threadIdx.x+off]; sq[threadIdx.x] += sq[threadIdx.x+off]; }
        __syncthreads();
    }
    if (threadIdx.x == 0) {
        const float inv_n = 1.0f / (float)(BB*LL);
        float mean = ss[0]*inv_n, var = sq[0]*inv_n - mean*mean;
        g_mean[c] = mean; g_rstd[c] = rsqrtf(var + BN_EPS);
    }
}

__global__ void bn_apply(const float* __restrict__ x, const float* __restrict__ bn_w,
                         const float* __restrict__ bn_b, const float* __restrict__ gamma,
                         float* __restrict__ out) {
    const size_t i4 = (size_t)blockIdx.x*blockDim.x + threadIdx.x;
    const size_t n4 = (size_t)BB*CC*LL/4;
    if (i4 >= n4) return;
    const int c = (int)((i4 / (LL/4)) % CC);
    const float w = bn_w[c]*g_rstd[c];
    const float bc = bn_b[c] - g_mean[c]*w;
    const float g = gamma[0];
    float4 v = ((const float4*)g_proj)[i4];
    float4 xr = ((const float4*)x)[i4];
    float4 y;
    y.x = g*(v.x*w + bc) + xr.x; y.y = g*(v.y*w + bc) + xr.y;
    y.z = g*(v.z*w + bc) + xr.z; y.w = g*(v.w*w + bc) + xr.w;
    y.x = y.x >= 0.f ? y.x : NEG_SLOPE*y.x; y.y = y.y >= 0.f ? y.y : NEG_SLOPE*y.y;
    y.z = y.z >= 0.f ? y.z : NEG_SLOPE*y.z; y.w = y.w >= 0.f ? y.w : NEG_SLOPE*y.w;
    ((float4*)out)[i4] = y;
}

// ------------------------- launch -------------------------
extern "C" void kernel_launch(void* const* d_in, const int* in_sizes, int n_in,
                              void* d_out, int out_size) {
    const float* x     = (const float*)d_in[0];
    const float* Wq    = (const float*)d_in[1];
    const float* Wk    = (const float*)d_in[2];
    const float* Wv    = (const float*)d_in[3];
    const float* Wo    = (const float*)d_in[4];
    const float* bn_w  = (const float*)d_in[5];
    const float* bn_b  = (const float*)d_in[6];
    const float* gamma = (const float*)d_in[7];
    float* out = (float*)d_out;

    __half *xt, *wqkv, *wo16, *ob;
    cudaGetSymbolAddress((void**)&xt,   g_xt);
    cudaGetSymbolAddress((void**)&wqkv, g_wqkv);
    cudaGetSymbolAddress((void**)&wo16, g_wo16);
    cudaGetSymbolAddress((void**)&ob,   g_ob);

    static bool once = false;
    if (!once) {
        cudaFuncSetAttribute(attn_mma, cudaFuncAttributeMaxDynamicSharedMemorySize, ATTN_SMEM);
        once = true;
    }

    const int nW = 512*256;
    cvt_f2h<<<(nW+255)/256, 256>>>(wqkv,        Wq, nW);
    cvt_f2h<<<(nW+255)/256, 256>>>(wqkv + nW,   Wk, nW);
    cvt_f2h<<<(nW+255)/256, 256>>>(wqkv + 2*nW, Wv, nW);
    cvt_f2h<<<(nW+255)/256, 256>>>(wo16,        Wo, nW);
    xpose<<<dim3(LL/32, CC/32, BB), dim3(32,8)>>>(x);

    gemm_mma<256,0><<<dim3(12, (BB*LL)/128), 256>>>(xt, wqkv);
    vtrans<<<dim3(LL/32, 2, BHT), dim3(32,8)>>>();
    attn_mma<<<dim3(LL/128, BHT), 256, ATTN_SMEM>>>();
    gemm_mma<512,1><<<dim3(2, (BB*LL)/128), 256>>>(ob, wo16);

    bn_stats<<<CC, 256>>>();
    const int n4 = BB*CC*LL/4;
    bn_apply<<<(n4+255)/256, 256>>>(x, bn_w, bn_b, gamma, out);
}

// round 6
// speedup vs baseline: 7.6883x; 1.0870x over previous
#include <cuda_runtime.h>
#include <cuda_fp16.h>
#include <math.h>
#include <stdint.h>

#define BB 4
#define CC 256
#define LL 2304
#define NHH 8
#define DKK 64
#define DD 512
#define BHT 32
#define BN_EPS 1e-5f
#define NEG_SLOPE 0.01f
#define QSCALE 0.18033688011112042f   // (1/sqrt(64)) * log2(e)

// ------------------------- scratch -------------------------
__device__ __half g_xt  [(size_t)BB*LL*CC];
__device__ __half g_wqkv[1536*CC];
__device__ __half g_wo16[CC*DD];
__device__ __half g_qb  [(size_t)BHT*LL*DKK];
__device__ __half g_kb  [(size_t)BHT*LL*DKK];
__device__ __half g_vb  [(size_t)BHT*LL*DKK];
__device__ __half g_vt  [(size_t)BHT*DKK*LL];
__device__ __half g_ob  [(size_t)BB*LL*DD];
__device__ float  g_proj[(size_t)BB*CC*LL];
__device__ float  g_mean[CC];
__device__ float  g_rstd[CC];

// ------------------------- helpers -------------------------
__device__ __forceinline__ float ex2f(float x) {
    float y; asm("ex2.approx.ftz.f32 %0, %1;" : "=f"(y) : "f"(x)); return y;
}
__device__ __forceinline__ void mma16816(float* c, const uint32_t* a, const uint32_t* b) {
    asm volatile("mma.sync.aligned.m16n8k16.row.col.f32.f16.f16.f32 "
        "{%0,%1,%2,%3}, {%4,%5,%6,%7}, {%8,%9}, {%0,%1,%2,%3};"
        : "+f"(c[0]), "+f"(c[1]), "+f"(c[2]), "+f"(c[3])
        : "r"(a[0]), "r"(a[1]), "r"(a[2]), "r"(a[3]), "r"(b[0]), "r"(b[1]));
}
__device__ __forceinline__ uint32_t packh2(float x, float y) {
    __half2 h = __halves2half2(__float2half(x), __float2half(y));
    return *(uint32_t*)&h;
}
__device__ __forceinline__ void cp16(const __half* dst, const __half* src) {
    uint32_t d = (uint32_t)__cvta_generic_to_shared(dst);
    asm volatile("cp.async.cg.shared.global [%0], [%1], 16;" :: "r"(d), "l"(src));
}
#define CP_COMMIT() asm volatile("cp.async.commit_group;" ::: "memory")
#define CP_WAIT(n)  asm volatile("cp.async.wait_group %0;" :: "n"(n) : "memory")

// ------------------------- prep kernels -------------------------
// Fused weight conversion: Wq|Wk|Wv -> g_wqkv, Wo -> g_wo16 (one launch)
__global__ void cvt_all(const float* __restrict__ Wq, const float* __restrict__ Wk,
                        const float* __restrict__ Wv, const float* __restrict__ Wo) {
    int i = blockIdx.x * blockDim.x + threadIdx.x;   // float4 units, 0..131071
    int seg = i >> 15, off = i & 32767;
    const float* src = (seg == 0) ? Wq : (seg == 1) ? Wk : (seg == 2) ? Wv : Wo;
    __half* dst = (seg < 3) ? (g_wqkv + seg * 131072) : g_wo16;
    float4 v = ((const float4*)src)[off];
    __half2 h0 = __floats2half2_rn(v.x, v.y), h1 = __floats2half2_rn(v.z, v.w);
    uint2 u; u.x = *(uint32_t*)&h0; u.y = *(uint32_t*)&h1;
    ((uint2*)dst)[off] = u;
}

__global__ void xpose(const float* __restrict__ x) {   // x[b][c][l] -> g_xt[b][l][c] fp16
    __shared__ float t[32][33];
    int b = blockIdx.z, c0 = blockIdx.y * 32, l0 = blockIdx.x * 32;
    int tx = threadIdx.x, ty = threadIdx.y;
    #pragma unroll
    for (int k = 0; k < 4; k++)
        t[ty + k*8][tx] = x[((size_t)b*CC + c0 + ty + k*8)*LL + l0 + tx];
    __syncthreads();
    #pragma unroll
    for (int k = 0; k < 4; k++)
        g_xt[((size_t)b*LL + l0 + ty + k*8)*CC + c0 + tx] = __float2half(t[tx][ty + k*8]);
}

__global__ void vtrans() {   // g_vb[bh][l][dk] -> g_vt[bh][dk][l]
    __shared__ __half t[32][33];
    int bh = blockIdx.z, d0 = blockIdx.y * 32, l0 = blockIdx.x * 32;
    int tx = threadIdx.x, ty = threadIdx.y;
    #pragma unroll
    for (int k = 0; k < 4; k++)
        t[ty + k*8][tx] = g_vb[((size_t)bh*LL + l0 + ty + k*8)*DKK + d0 + tx];
    __syncthreads();
    #pragma unroll
    for (int k = 0; k < 4; k++)
        g_vt[((size_t)bh*DKK + d0 + ty + k*8)*LL + l0 + tx] = t[tx][ty + k*8];
}

// ------------------------- mma GEMM -------------------------
#define ASTR 72
template<int KH, int MODE>
__global__ void __launch_bounds__(256) gemm_mma(const __half* __restrict__ Ag,
                                               const __half* __restrict__ Bg) {
    __shared__ char smem_raw[2 * 128 * ASTR * 2];   // 36864 B
    __half* As = (__half*)smem_raw;
    __half* Bs = As + 128 * ASTR;

    const int tid = threadIdx.x;
    const int lane = tid & 31, wid = tid >> 5;
    const int wm = wid >> 1, wn = wid & 1;          // 4 x 2
    const int m0 = blockIdx.y * 128, n0 = blockIdx.x * 128;
    const int gr = lane >> 2, gc = lane & 3;

    float acc[2][8][4];
    #pragma unroll
    for (int i = 0; i < 2; i++)
        #pragma unroll
        for (int j = 0; j < 8; j++)
            #pragma unroll
            for (int u = 0; u < 4; u++) acc[i][j][u] = 0.f;

    for (int kc = 0; kc < KH; kc += 64) {
        __syncthreads();
        #pragma unroll
        for (int t = 0; t < 4; t++) {               // 128 rows x 8 int4
            int i = tid + t*256, r = i >> 3, c = i & 7;
            *(int4*)(As + r*ASTR + c*8) = *(const int4*)(Ag + (size_t)(m0+r)*KH + kc + c*8);
            *(int4*)(Bs + r*ASTR + c*8) = *(const int4*)(Bg + (size_t)(n0+r)*KH + kc + c*8);
        }
        __syncthreads();
        #pragma unroll
        for (int kk = 0; kk < 64; kk += 16) {
            uint32_t a[2][4], b[8][2];
            #pragma unroll
            for (int mt = 0; mt < 2; mt++) {
                const __half* p = As + (wm*32 + mt*16 + gr)*ASTR + kk + 2*gc;
                a[mt][0] = *(const uint32_t*)p;
                a[mt][1] = *(const uint32_t*)(p + 8*ASTR);
                a[mt][2] = *(const uint32_t*)(p + 8);
                a[mt][3] = *(const uint32_t*)(p + 8*ASTR + 8);
            }
            #pragma unroll
            for (int nt = 0; nt < 8; nt++) {
                const __half* p = Bs + (wn*64 + nt*8 + gr)*ASTR + kk + 2*gc;
                b[nt][0] = *(const uint32_t*)p;
                b[nt][1] = *(const uint32_t*)(p + 8);
            }
            #pragma unroll
            for (int mt = 0; mt < 2; mt++)
                #pragma unroll
                for (int nt = 0; nt < 8; nt++)
                    mma16816(acc[mt][nt], a[mt], b[nt]);
        }
    }

    if (MODE == 0) {
        const int b = m0 / LL, lbase = m0 % LL;
        #pragma unroll
        for (int mt = 0; mt < 2; mt++)
            #pragma unroll
            for (int half = 0; half < 2; half++) {
                int l = lbase + wm*32 + mt*16 + gr + half*8;
                #pragma unroll
                for (int nt = 0; nt < 8; nt++) {
                    int n = n0 + wn*64 + nt*8 + 2*gc;
                    int which = n >> 9, h = (n & 511) >> 6, dk = n & 63;
                    __half* dst = (which == 0) ? g_qb : (which == 1) ? g_kb : g_vb;
                    float sc = (which == 0) ? QSCALE : 1.0f;
                    uint32_t v = packh2(acc[mt][nt][half*2] * sc, acc[mt][nt][half*2+1] * sc);
                    *(uint32_t*)(dst + ((size_t)(b*NHH + h)*LL + l)*DKK + dk) = v;
                }
            }
    } else {
        float* stage = (float*)smem_raw;            // [64][132] floats
        const int b = m0 / LL, l0 = m0 % LL;
        #pragma unroll
        for (int p = 0; p < 2; p++) {
            __syncthreads();
            if (wn == p) {
                #pragma unroll
                for (int mt = 0; mt < 2; mt++)
                    #pragma unroll
                    for (int nt = 0; nt < 8; nt++)
                        #pragma unroll
                        for (int u = 0; u < 4; u++) {
                            int row = wm*32 + mt*16 + gr + (u >> 1)*8;
                            int col = nt*8 + 2*gc + (u & 1);
                            stage[col*132 + row] = acc[mt][nt][u];
                        }
            }
            __syncthreads();
            #pragma unroll
            for (int k = 0; k < 8; k++) {
                int idx = tid + k*256;
                int nl = idx >> 5, mw = idx & 31;
                *(float4*)(g_proj + ((size_t)b*CC + n0 + p*64 + nl)*LL + l0 + mw*4) =
                    *(const float4*)(stage + nl*132 + mw*4);
            }
        }
    }
}

// ------------------------- fused flash attention -------------------------
// CTA: 256 q-rows, 8 warps x 32 q-rows (2 groups of 16). k-tile = 64.
// K/V b-fragments shared across both q-groups (2x LDS traffic cut).
// cp.async double-buffered K/V tiles. Softmax exp via h2exp2 (f16x2 MUFU).
#define KT 64
#define QT 256
#define STR 72
#define Q_HALVES (QT*STR)                 // 18432
#define KV_HALVES (64*STR)                // 4608
#define ATTN_SMEM ((Q_HALVES + 4*KV_HALVES) * 2)   // 73728 B

__global__ void __launch_bounds__(256, 1) attn_mma() {
    extern __shared__ __half sh[];
    __half* Qs  = sh;
    __half* Kb0 = sh + Q_HALVES;
    __half* Kb1 = Kb0 + KV_HALVES;
    __half* Vb0 = Kb1 + KV_HALVES;
    __half* Vb1 = Vb0 + KV_HALVES;

    const int tid = threadIdx.x;
    const int lane = tid & 31, wid = tid >> 5;
    const int gr = lane >> 2, gc = lane & 3;
    const int bh = blockIdx.y, q0 = blockIdx.x * QT;
    const __half* Qp = g_qb + (size_t)bh*LL*DKK;
    const __half* Kp = g_kb + (size_t)bh*LL*DKK;
    const __half* Vp = g_vt + (size_t)bh*DKK*LL;

    // Q tile -> smem (256 rows x 64 halves)
    #pragma unroll
    for (int t = 0; t < 8; t++) {
        int i = tid + t*256, r = i >> 3, c = i & 7;
        *(int4*)(Qs + r*STR + c*8) = *(const int4*)(Qp + (size_t)(q0+r)*DKK + c*8);
    }
    // kick off first K/V tile while Q settles
    #pragma unroll
    for (int t = 0; t < 2; t++) {
        int i = tid + t*256, r = i >> 3, c = i & 7;
        cp16(Kb0 + r*STR + c*8, Kp + (size_t)r*DKK + c*8);
        cp16(Vb0 + r*STR + c*8, Vp + (size_t)r*LL + c*8);
    }
    CP_COMMIT();
    __syncthreads();

    // Q fragments: warp owns rows wid*32 + g*16 .. +15
    uint32_t aq[2][4][4];
    #pragma unroll
    for (int g = 0; g < 2; g++)
        #pragma unroll
        for (int kk = 0; kk < 4; kk++) {
            const __half* p = Qs + (wid*32 + g*16 + gr)*STR + kk*16 + 2*gc;
            aq[g][kk][0] = *(const uint32_t*)p;
            aq[g][kk][1] = *(const uint32_t*)(p + 8*STR);
            aq[g][kk][2] = *(const uint32_t*)(p + 8);
            aq[g][kk][3] = *(const uint32_t*)(p + 8*STR + 8);
        }

    float o[2][8][4];
    #pragma unroll
    for (int g = 0; g < 2; g++)
        #pragma unroll
        for (int j = 0; j < 8; j++)
            #pragma unroll
            for (int u = 0; u < 4; u++) o[g][j][u] = 0.f;
    float m2[2][2] = {{-1e30f,-1e30f},{-1e30f,-1e30f}};
    float l2[2][2] = {{0.f,0.f},{0.f,0.f}};

    const int NTILES = LL / KT;   // 36
    for (int kt = 0; kt < NTILES; kt++) {
        __half* Ks = (kt & 1) ? Kb1 : Kb0;
        __half* Vs = (kt & 1) ? Vb1 : Vb0;
        if (kt + 1 < NTILES) {
            __half* Kn = (kt & 1) ? Kb0 : Kb1;
            __half* Vn = (kt & 1) ? Vb0 : Vb1;
            int k0n = (kt + 1) * KT;
            #pragma unroll
            for (int t = 0; t < 2; t++) {
                int i = tid + t*256, r = i >> 3, c = i & 7;
                cp16(Kn + r*STR + c*8, Kp + (size_t)(k0n + r)*DKK + c*8);
                cp16(Vn + r*STR + c*8, Vp + (size_t)r*LL + k0n + c*8);
            }
            CP_COMMIT();
            CP_WAIT(1);
        } else {
            CP_WAIT(0);
        }
        __syncthreads();

        // S = Q Kt for both groups, K fragments loaded once
        float s[2][8][4];
        #pragma unroll
        for (int g = 0; g < 2; g++)
            #pragma unroll
            for (int j = 0; j < 8; j++)
                #pragma unroll
                for (int u = 0; u < 4; u++) s[g][j][u] = 0.f;
        #pragma unroll
        for (int kk = 0; kk < 4; kk++)
            #pragma unroll
            for (int nt = 0; nt < 8; nt++) {
                uint32_t b[2];
                const __half* p = Ks + (nt*8 + gr)*STR + kk*16 + 2*gc;
                b[0] = *(const uint32_t*)p;
                b[1] = *(const uint32_t*)(p + 8);
                mma16816(s[0][nt], aq[0][kk], b);
                mma16816(s[1][nt], aq[1][kk], b);
            }

        // online softmax per group; build P fragments via f16x2 exp2
        uint32_t ap[2][4][4];
        float sc[2][2];
        #pragma unroll
        for (int g = 0; g < 2; g++) {
            #pragma unroll
            for (int hf = 0; hf < 2; hf++) {
                float mx = -1e30f;
                #pragma unroll
                for (int nt = 0; nt < 8; nt++)
                    mx = fmaxf(mx, fmaxf(s[g][nt][hf*2], s[g][nt][hf*2+1]));
                mx = fmaxf(mx, __shfl_xor_sync(0xffffffff, mx, 1));
                mx = fmaxf(mx, __shfl_xor_sync(0xffffffff, mx, 2));
                float mn = fmaxf(m2[g][hf], mx);
                sc[g][hf] = ex2f(m2[g][hf] - mn);
                m2[g][hf] = mn;
            }
            float ls0 = 0.f, ls1 = 0.f;
            #pragma unroll
            for (int nt = 0; nt < 8; nt++) {
                __half2 e0 = h2exp2(__floats2half2_rn(s[g][nt][0] - m2[g][0],
                                                      s[g][nt][1] - m2[g][0]));
                __half2 e1 = h2exp2(__floats2half2_rn(s[g][nt][2] - m2[g][1],
                                                      s[g][nt][3] - m2[g][1]));
                ap[g][nt >> 1][(nt & 1)*2]     = *(uint32_t*)&e0;
                ap[g][nt >> 1][(nt & 1)*2 + 1] = *(uint32_t*)&e1;
                float2 f0 = __half22float2(e0), f1 = __half22float2(e1);
                ls0 += f0.x + f0.y;
                ls1 += f1.x + f1.y;
            }
            ls0 += __shfl_xor_sync(0xffffffff, ls0, 1);
            ls0 += __shfl_xor_sync(0xffffffff, ls0, 2);
            ls1 += __shfl_xor_sync(0xffffffff, ls1, 1);
            ls1 += __shfl_xor_sync(0xffffffff, ls1, 2);
            l2[g][0] = l2[g][0] * sc[g][0] + ls0;
            l2[g][1] = l2[g][1] * sc[g][1] + ls1;
            #pragma unroll
            for (int nt = 0; nt < 8; nt++) {
                o[g][nt][0] *= sc[g][0]; o[g][nt][1] *= sc[g][0];
                o[g][nt][2] *= sc[g][1]; o[g][nt][3] *= sc[g][1];
            }
        }

        // PV: V fragments loaded once, serve both groups
        #pragma unroll
        for (int kk = 0; kk < 4; kk++)
            #pragma unroll
            for (int nt = 0; nt < 8; nt++) {
                uint32_t b[2];
                const __half* p = Vs + (nt*8 + gr)*STR + kk*16 + 2*gc;
                b[0] = *(const uint32_t*)p;
                b[1] = *(const uint32_t*)(p + 8);
                mma16816(o[0][nt], ap[0][kk], b);
                mma16816(o[1][nt], ap[1][kk], b);
            }
        __syncthreads();
    }

    // normalize + store: g_ob[b][l][h*64+d]
    const int b = bh >> 3, h = bh & 7;
    #pragma unroll
    for (int g = 0; g < 2; g++)
        #pragma unroll
        for (int hf = 0; hf < 2; hf++) {
            int l = q0 + wid*32 + g*16 + gr + hf*8;
            float inv = 1.0f / l2[g][hf];
            __half* dst = g_ob + ((size_t)b*LL + l)*DD + h*DKK;
            #pragma unroll
            for (int nt = 0; nt < 8; nt++)
                *(uint32_t*)(dst + nt*8 + 2*gc) =
                    packh2(o[g][nt][hf*2]*inv, o[g][nt][hf*2+1]*inv);
        }
}

// ------------------------- BN -------------------------
__global__ void bn_stats() {
    const int c = blockIdx.x;
    float sum = 0.f, sumsq = 0.f;
    for (int b = 0; b < BB; b++) {
        const float* p = g_proj + ((size_t)b*CC + c)*LL;
        for (int i = threadIdx.x; i < LL; i += blockDim.x) {
            float v = p[i]; sum += v; sumsq += v*v;
        }
    }
    __shared__ float ss[256], sq[256];
    ss[threadIdx.x] = sum; sq[threadIdx.x] = sumsq;
    __syncthreads();
    for (int off = 128; off > 0; off >>= 1) {
        if (threadIdx.x < off) { ss[threadIdx.x] += ss[threadIdx.x+off]; sq[threadIdx.x] += sq[threadIdx.x+off]; }
        __syncthreads();
    }
    if (threadIdx.x == 0) {
        const float inv_n = 1.0f / (float)(BB*LL);
        float mean = ss[0]*inv_n, var = sq[0]*inv_n - mean*mean;
        g_mean[c] = mean; g_rstd[c] = rsqrtf(var + BN_EPS);
    }
}

__global__ void bn_apply(const float* __restrict__ x, const float* __restrict__ bn_w,
                         const float* __restrict__ bn_b, const float* __restrict__ gamma,
                         float* __restrict__ out) {
    const size_t i4 = (size_t)blockIdx.x*blockDim.x + threadIdx.x;
    const size_t n4 = (size_t)BB*CC*LL/4;
    if (i4 >= n4) return;
    const int c = (int)((i4 / (LL/4)) % CC);
    const float w = bn_w[c]*g_rstd[c];
    const float bc = bn_b[c] - g_mean[c]*w;
    const float g = gamma[0];
    float4 v = ((const float4*)g_proj)[i4];
    float4 xr = ((const float4*)x)[i4];
    float4 y;
    y.x = g*(v.x*w + bc) + xr.x; y.y = g*(v.y*w + bc) + xr.y;
    y.z = g*(v.z*w + bc) + xr.z; y.w = g*(v.w*w + bc) + xr.w;
    y.x = y.x >= 0.f ? y.x : NEG_SLOPE*y.x; y.y = y.y >= 0.f ? y.y : NEG_SLOPE*y.y;
    y.z = y.z >= 0.f ? y.z : NEG_SLOPE*y.z; y.w = y.w >= 0.f ? y.w : NEG_SLOPE*y.w;
    ((float4*)out)[i4] = y;
}

// ------------------------- launch -------------------------
extern "C" void kernel_launch(void* const* d_in, const int* in_sizes, int n_in,
                              void* d_out, int out_size) {
    const float* x     = (const float*)d_in[0];
    const float* Wq    = (const float*)d_in[1];
    const float* Wk    = (const float*)d_in[2];
    const float* Wv    = (const float*)d_in[3];
    const float* Wo    = (const float*)d_in[4];
    const float* bn_w  = (const float*)d_in[5];
    const float* bn_b  = (const float*)d_in[6];
    const float* gamma = (const float*)d_in[7];
    float* out = (float*)d_out;

    __half *xt, *wqkv, *wo16, *ob;
    cudaGetSymbolAddress((void**)&xt,   g_xt);
    cudaGetSymbolAddress((void**)&wqkv, g_wqkv);
    cudaGetSymbolAddress((void**)&wo16, g_wo16);
    cudaGetSymbolAddress((void**)&ob,   g_ob);

    static bool once = false;
    if (!once) {
        cudaFuncSetAttribute(attn_mma, cudaFuncAttributeMaxDynamicSharedMemorySize, ATTN_SMEM);
        once = true;
    }

    cvt_all<<<512, 256>>>(Wq, Wk, Wv, Wo);
    xpose<<<dim3(LL/32, CC/32, BB), dim3(32,8)>>>(x);

    gemm_mma<256,0><<<dim3(12, (BB*LL)/128), 256>>>(xt, wqkv);
    vtrans<<<dim3(LL/32, 2, BHT), dim3(32,8)>>>();
    attn_mma<<<dim3(LL/QT, BHT), 256, ATTN_SMEM>>>();
    gemm_mma<512,1><<<dim3(2, (BB*LL)/128), 256>>>(ob, wo16);

    bn_stats<<<CC, 256>>>();
    const int n4 = BB*CC*LL/4;
    bn_apply<<<(n4+255)/256, 256>>>(x, bn_w, bn_b, gamma, out);
}

// round 7
// speedup vs baseline: 8.0953x; 1.0529x over previous
#include <cuda_runtime.h>
#include <cuda_fp16.h>
#include <math.h>
#include <stdint.h>

#define BB 4
#define CC 256
#define LL 2304
#define NHH 8
#define DKK 64
#define DD 512
#define BHT 32
#define BN_EPS 1e-5f
#define NEG_SLOPE 0.01f
#define QSCALE 0.18033688011112042f   // (1/sqrt(64)) * log2(e)

// ------------------------- scratch -------------------------
__device__ __half g_xt  [(size_t)BB*LL*CC];
__device__ __half g_wqkv[1536*CC];
__device__ __half g_wo16[CC*DD];
__device__ __half g_qb  [(size_t)BHT*LL*DKK];
__device__ __half g_kb  [(size_t)BHT*LL*DKK];
__device__ __half g_vb  [(size_t)BHT*LL*DKK];
__device__ __half g_ob  [(size_t)BB*LL*DD];
__device__ float  g_proj[(size_t)BB*CC*LL];
__device__ float  g_sum[CC];
__device__ float  g_sumsq[CC];
__device__ float  g_mean[CC];
__device__ float  g_rstd[CC];

// ------------------------- helpers -------------------------
__device__ __forceinline__ float ex2f(float x) {
    float y; asm("ex2.approx.ftz.f32 %0, %1;" : "=f"(y) : "f"(x)); return y;
}
__device__ __forceinline__ void mma16816(float* c, const uint32_t* a, const uint32_t* b) {
    asm volatile("mma.sync.aligned.m16n8k16.row.col.f32.f16.f16.f32 "
        "{%0,%1,%2,%3}, {%4,%5,%6,%7}, {%8,%9}, {%0,%1,%2,%3};"
        : "+f"(c[0]), "+f"(c[1]), "+f"(c[2]), "+f"(c[3])
        : "r"(a[0]), "r"(a[1]), "r"(a[2]), "r"(a[3]), "r"(b[0]), "r"(b[1]));
}
__device__ __forceinline__ uint32_t packh2(float x, float y) {
    __half2 h = __halves2half2(__float2half(x), __float2half(y));
    return *(uint32_t*)&h;
}
__device__ __forceinline__ void cp16(const __half* dst, const __half* src) {
    uint32_t d = (uint32_t)__cvta_generic_to_shared(dst);
    asm volatile("cp.async.cg.shared.global [%0], [%1], 16;" :: "r"(d), "l"(src));
}
#define CP_COMMIT() asm volatile("cp.async.commit_group;" ::: "memory")
#define CP_WAIT(n)  asm volatile("cp.async.wait_group %0;" :: "n"(n) : "memory")

__device__ __forceinline__ void ldsm4(uint32_t* r, uint32_t addr) {
    asm volatile("ldmatrix.sync.aligned.m8n8.x4.shared.b16 {%0,%1,%2,%3}, [%4];"
        : "=r"(r[0]), "=r"(r[1]), "=r"(r[2]), "=r"(r[3]) : "r"(addr));
}
__device__ __forceinline__ void ldsm4t(uint32_t* r, uint32_t addr) {
    asm volatile("ldmatrix.sync.aligned.m8n8.x4.trans.shared.b16 {%0,%1,%2,%3}, [%4];"
        : "=r"(r[0]), "=r"(r[1]), "=r"(r[2]), "=r"(r[3]) : "r"(addr));
}

// ------------------------- prep kernels -------------------------
__global__ void cvt_all(const float* __restrict__ Wq, const float* __restrict__ Wk,
                        const float* __restrict__ Wv, const float* __restrict__ Wo) {
    int i = blockIdx.x * blockDim.x + threadIdx.x;   // float4 units
    int seg = i >> 15, off = i & 32767;
    const float* src = (seg == 0) ? Wq : (seg == 1) ? Wk : (seg == 2) ? Wv : Wo;
    __half* dst = (seg < 3) ? (g_wqkv + seg * 131072) : g_wo16;
    float4 v = ((const float4*)src)[off];
    __half2 h0 = __floats2half2_rn(v.x, v.y), h1 = __floats2half2_rn(v.z, v.w);
    uint2 u; u.x = *(uint32_t*)&h0; u.y = *(uint32_t*)&h1;
    ((uint2*)dst)[off] = u;
}

__global__ void zero_sums() {
    int i = threadIdx.x;
    if (i < CC) { g_sum[i] = 0.f; g_sumsq[i] = 0.f; }
}

__global__ void xpose(const float* __restrict__ x) {   // x[b][c][l] -> g_xt[b][l][c] fp16
    __shared__ float t[32][33];
    int b = blockIdx.z, c0 = blockIdx.y * 32, l0 = blockIdx.x * 32;
    int tx = threadIdx.x, ty = threadIdx.y;
    #pragma unroll
    for (int k = 0; k < 4; k++)
        t[ty + k*8][tx] = x[((size_t)b*CC + c0 + ty + k*8)*LL + l0 + tx];
    __syncthreads();
    #pragma unroll
    for (int k = 0; k < 4; k++)
        g_xt[((size_t)b*LL + l0 + ty + k*8)*CC + c0 + tx] = __float2half(t[tx][ty + k*8]);
}

// ------------------------- mma GEMM -------------------------
#define ASTR 72
template<int KH, int MODE>
__global__ void __launch_bounds__(256) gemm_mma(const __half* __restrict__ Ag,
                                               const __half* __restrict__ Bg) {
    __shared__ char smem_raw[2 * 128 * ASTR * 2];   // 36864 B
    __half* As = (__half*)smem_raw;
    __half* Bs = As + 128 * ASTR;

    const int tid = threadIdx.x;
    const int lane = tid & 31, wid = tid >> 5;
    const int wm = wid >> 1, wn = wid & 1;          // 4 x 2
    const int m0 = blockIdx.y * 128, n0 = blockIdx.x * 128;
    const int gr = lane >> 2, gc = lane & 3;

    float acc[2][8][4];
    #pragma unroll
    for (int i = 0; i < 2; i++)
        #pragma unroll
        for (int j = 0; j < 8; j++)
            #pragma unroll
            for (int u = 0; u < 4; u++) acc[i][j][u] = 0.f;

    for (int kc = 0; kc < KH; kc += 64) {
        __syncthreads();
        #pragma unroll
        for (int t = 0; t < 4; t++) {
            int i = tid + t*256, r = i >> 3, c = i & 7;
            *(int4*)(As + r*ASTR + c*8) = *(const int4*)(Ag + (size_t)(m0+r)*KH + kc + c*8);
            *(int4*)(Bs + r*ASTR + c*8) = *(const int4*)(Bg + (size_t)(n0+r)*KH + kc + c*8);
        }
        __syncthreads();
        #pragma unroll
        for (int kk = 0; kk < 64; kk += 16) {
            uint32_t a[2][4], b[8][2];
            #pragma unroll
            for (int mt = 0; mt < 2; mt++) {
                const __half* p = As + (wm*32 + mt*16 + gr)*ASTR + kk + 2*gc;
                a[mt][0] = *(const uint32_t*)p;
                a[mt][1] = *(const uint32_t*)(p + 8*ASTR);
                a[mt][2] = *(const uint32_t*)(p + 8);
                a[mt][3] = *(const uint32_t*)(p + 8*ASTR + 8);
            }
            #pragma unroll
            for (int nt = 0; nt < 8; nt++) {
                const __half* p = Bs + (wn*64 + nt*8 + gr)*ASTR + kk + 2*gc;
                b[nt][0] = *(const uint32_t*)p;
                b[nt][1] = *(const uint32_t*)(p + 8);
            }
            #pragma unroll
            for (int mt = 0; mt < 2; mt++)
                #pragma unroll
                for (int nt = 0; nt < 8; nt++)
                    mma16816(acc[mt][nt], a[mt], b[nt]);
        }
    }

    if (MODE == 0) {
        const int b = m0 / LL, lbase = m0 % LL;
        #pragma unroll
        for (int mt = 0; mt < 2; mt++)
            #pragma unroll
            for (int half = 0; half < 2; half++) {
                int l = lbase + wm*32 + mt*16 + gr + half*8;
                #pragma unroll
                for (int nt = 0; nt < 8; nt++) {
                    int n = n0 + wn*64 + nt*8 + 2*gc;
                    int which = n >> 9, h = (n & 511) >> 6, dk = n & 63;
                    __half* dst = (which == 0) ? g_qb : (which == 1) ? g_kb : g_vb;
                    float sc = (which == 0) ? QSCALE : 1.0f;
                    uint32_t v = packh2(acc[mt][nt][half*2] * sc, acc[mt][nt][half*2+1] * sc);
                    *(uint32_t*)(dst + ((size_t)(b*NHH + h)*LL + l)*DKK + dk) = v;
                }
            }
    } else {
        float* stage = (float*)smem_raw;            // [64][132] floats
        const int b = m0 / LL, l0 = m0 % LL;
        #pragma unroll
        for (int p = 0; p < 2; p++) {
            __syncthreads();
            if (wn == p) {
                #pragma unroll
                for (int mt = 0; mt < 2; mt++)
                    #pragma unroll
                    for (int nt = 0; nt < 8; nt++)
                        #pragma unroll
                        for (int u = 0; u < 4; u++) {
                            int row = wm*32 + mt*16 + gr + (u >> 1)*8;
                            int col = nt*8 + 2*gc + (u & 1);
                            stage[col*132 + row] = acc[mt][nt][u];
                        }
            }
            __syncthreads();
            #pragma unroll
            for (int k = 0; k < 8; k++) {
                int idx = tid + k*256;
                int nl = idx >> 5, mw = idx & 31;
                float4 v = *(const float4*)(stage + nl*132 + mw*4);
                *(float4*)(g_proj + ((size_t)b*CC + n0 + p*64 + nl)*LL + l0 + mw*4) = v;
                // fused BN partial sums: lanes of a warp share channel nl
                float ss = v.x + v.y + v.z + v.w;
                float sq = v.x*v.x + v.y*v.y + v.z*v.z + v.w*v.w;
                #pragma unroll
                for (int off = 16; off > 0; off >>= 1) {
                    ss += __shfl_xor_sync(0xffffffff, ss, off);
                    sq += __shfl_xor_sync(0xffffffff, sq, off);
                }
                if (lane == 0) {
                    atomicAdd(&g_sum[n0 + p*64 + nl], ss);
                    atomicAdd(&g_sumsq[n0 + p*64 + nl], sq);
                }
            }
        }
    }
}

// ------------------------- fused flash attention -------------------------
// CTA: 256 q-rows, 8 warps x 32 q-rows (2 groups of 16). k-tile = 64.
// K and V both in [l][dk] layout; V B-frags built via ldmatrix.trans.
#define KT 64
#define QT 256
#define STR 72
#define Q_HALVES (QT*STR)
#define KV_HALVES (64*STR)
#define ATTN_SMEM ((Q_HALVES + 4*KV_HALVES) * 2)   // 73728 B

__global__ void __launch_bounds__(256, 1) attn_mma() {
    extern __shared__ __half sh[];
    __half* Qs  = sh;
    __half* Kb0 = sh + Q_HALVES;
    __half* Kb1 = Kb0 + KV_HALVES;
    __half* Vb0 = Kb1 + KV_HALVES;
    __half* Vb1 = Vb0 + KV_HALVES;

    const int tid = threadIdx.x;
    const int lane = tid & 31, wid = tid >> 5;
    const int gr = lane >> 2, gc = lane & 3;
    const int lm = lane >> 3, lr = lane & 7;      // ldmatrix lane mapping
    const int bh = blockIdx.y, q0 = blockIdx.x * QT;
    const __half* Qp = g_qb + (size_t)bh*LL*DKK;
    const __half* Kp = g_kb + (size_t)bh*LL*DKK;
    const __half* Vp = g_vb + (size_t)bh*LL*DKK;

    // Q tile -> smem (256 rows x 64 halves)
    #pragma unroll
    for (int t = 0; t < 8; t++) {
        int i = tid + t*256, r = i >> 3, c = i & 7;
        *(int4*)(Qs + r*STR + c*8) = *(const int4*)(Qp + (size_t)(q0+r)*DKK + c*8);
    }
    // first K/V tile
    #pragma unroll
    for (int t = 0; t < 2; t++) {
        int i = tid + t*256, r = i >> 3, c = i & 7;
        cp16(Kb0 + r*STR + c*8, Kp + (size_t)r*DKK + c*8);
        cp16(Vb0 + r*STR + c*8, Vp + (size_t)r*DKK + c*8);
    }
    CP_COMMIT();
    __syncthreads();

    const uint32_t qsb = (uint32_t)__cvta_generic_to_shared(Qs);

    // Q fragments via ldmatrix.x4: [2 groups][4 kk][4 regs]
    uint32_t aq[2][4][4];
    #pragma unroll
    for (int g = 0; g < 2; g++)
        #pragma unroll
        for (int kk = 0; kk < 4; kk++) {
            uint32_t addr = qsb + 2u*((wid*32 + g*16 + (lm & 1)*8 + lr)*STR
                                      + kk*16 + (lm >> 1)*8);
            ldsm4(aq[g][kk], addr);
        }

    float o[2][8][4];
    #pragma unroll
    for (int g = 0; g < 2; g++)
        #pragma unroll
        for (int j = 0; j < 8; j++)
            #pragma unroll
            for (int u = 0; u < 4; u++) o[g][j][u] = 0.f;
    float m2[2][2] = {{-1e30f,-1e30f},{-1e30f,-1e30f}};
    float l2[2][2] = {{0.f,0.f},{0.f,0.f}};

    const int NTILES = LL / KT;   // 36
    for (int kt = 0; kt < NTILES; kt++) {
        __half* Ks = (kt & 1) ? Kb1 : Kb0;
        __half* Vs = (kt & 1) ? Vb1 : Vb0;
        if (kt + 1 < NTILES) {
            __half* Kn = (kt & 1) ? Kb0 : Kb1;
            __half* Vn = (kt & 1) ? Vb0 : Vb1;
            int k0n = (kt + 1) * KT;
            #pragma unroll
            for (int t = 0; t < 2; t++) {
                int i = tid + t*256, r = i >> 3, c = i & 7;
                cp16(Kn + r*STR + c*8, Kp + (size_t)(k0n + r)*DKK + c*8);
                cp16(Vn + r*STR + c*8, Vp + (size_t)(k0n + r)*DKK + c*8);
            }
            CP_COMMIT();
            CP_WAIT(1);
        } else {
            CP_WAIT(0);
        }
        __syncthreads();

        const uint32_t ksb = (uint32_t)__cvta_generic_to_shared(Ks);
        const uint32_t vsb = (uint32_t)__cvta_generic_to_shared(Vs);

        // S = Q Kt : K b-frags via ldmatrix.x4 (2 n-tiles per instr)
        float s[2][8][4];
        #pragma unroll
        for (int g = 0; g < 2; g++)
            #pragma unroll
            for (int j = 0; j < 8; j++)
                #pragma unroll
                for (int u = 0; u < 4; u++) s[g][j][u] = 0.f;
        #pragma unroll
        for (int kk = 0; kk < 4; kk++)
            #pragma unroll
            for (int ntp = 0; ntp < 4; ntp++) {
                uint32_t bb[4];
                uint32_t addr = ksb + 2u*(((ntp*2 + (lm >> 1))*8 + lr)*STR
                                          + kk*16 + (lm & 1)*8);
                ldsm4(bb, addr);
                mma16816(s[0][ntp*2],   aq[0][kk], bb);
                mma16816(s[1][ntp*2],   aq[1][kk], bb);
                mma16816(s[0][ntp*2+1], aq[0][kk], bb + 2);
                mma16816(s[1][ntp*2+1], aq[1][kk], bb + 2);
            }

        // online softmax per group; P fragments via f16x2 exp2
        uint32_t ap[2][4][4];
        float sc[2][2];
        #pragma unroll
        for (int g = 0; g < 2; g++) {
            #pragma unroll
            for (int hf = 0; hf < 2; hf++) {
                float mx = -1e30f;
                #pragma unroll
                for (int nt = 0; nt < 8; nt++)
                    mx = fmaxf(mx, fmaxf(s[g][nt][hf*2], s[g][nt][hf*2+1]));
                mx = fmaxf(mx, __shfl_xor_sync(0xffffffff, mx, 1));
                mx = fmaxf(mx, __shfl_xor_sync(0xffffffff, mx, 2));
                float mn = fmaxf(m2[g][hf], mx);
                sc[g][hf] = ex2f(m2[g][hf] - mn);
                m2[g][hf] = mn;
            }
            float ls0 = 0.f, ls1 = 0.f;
            #pragma unroll
            for (int nt = 0; nt < 8; nt++) {
                __half2 e0 = h2exp2(__floats2half2_rn(s[g][nt][0] - m2[g][0],
                                                      s[g][nt][1] - m2[g][0]));
                __half2 e1 = h2exp2(__floats2half2_rn(s[g][nt][2] - m2[g][1],
                                                      s[g][nt][3] - m2[g][1]));
                ap[g][nt >> 1][(nt & 1)*2]     = *(uint32_t*)&e0;
                ap[g][nt >> 1][(nt & 1)*2 + 1] = *(uint32_t*)&e1;
                float2 f0 = __half22float2(e0), f1 = __half22float2(e1);
                ls0 += f0.x + f0.y;
                ls1 += f1.x + f1.y;
            }
            ls0 += __shfl_xor_sync(0xffffffff, ls0, 1);
            ls0 += __shfl_xor_sync(0xffffffff, ls0, 2);
            ls1 += __shfl_xor_sync(0xffffffff, ls1, 1);
            ls1 += __shfl_xor_sync(0xffffffff, ls1, 2);
            l2[g][0] = l2[g][0] * sc[g][0] + ls0;
            l2[g][1] = l2[g][1] * sc[g][1] + ls1;
            #pragma unroll
            for (int nt = 0; nt < 8; nt++) {
                o[g][nt][0] *= sc[g][0]; o[g][nt][1] *= sc[g][0];
                o[g][nt][2] *= sc[g][1]; o[g][nt][3] *= sc[g][1];
            }
        }

        // PV: V b-frags via ldmatrix.x4.trans from [l][dk] layout
        #pragma unroll
        for (int kk = 0; kk < 4; kk++)
            #pragma unroll
            for (int ntp = 0; ntp < 4; ntp++) {
                uint32_t bb[4];
                uint32_t addr = vsb + 2u*((kk*16 + (lm & 1)*8 + lr)*STR
                                          + (ntp*2 + (lm >> 1))*8);
                ldsm4t(bb, addr);
                mma16816(o[0][ntp*2],   ap[0][kk], bb);
                mma16816(o[1][ntp*2],   ap[1][kk], bb);
                mma16816(o[0][ntp*2+1], ap[0][kk], bb + 2);
                mma16816(o[1][ntp*2+1], ap[1][kk], bb + 2);
            }
        __syncthreads();
    }

    // normalize + store: g_ob[b][l][h*64+d]
    const int b = bh >> 3, h = bh & 7;
    #pragma unroll
    for (int g = 0; g < 2; g++)
        #pragma unroll
        for (int hf = 0; hf < 2; hf++) {
            int l = q0 + wid*32 + g*16 + gr + hf*8;
            float inv = 1.0f / l2[g][hf];
            __half* dst = g_ob + ((size_t)b*LL + l)*DD + h*DKK;
            #pragma unroll
            for (int nt = 0; nt < 8; nt++)
                *(uint32_t*)(dst + nt*8 + 2*gc) =
                    packh2(o[g][nt][hf*2]*inv, o[g][nt][hf*2+1]*inv);
        }
}

// ------------------------- BN -------------------------
__global__ void bn_finalize() {
    int c = threadIdx.x;
    if (c < CC) {
        const float inv_n = 1.0f / (float)(BB*LL);
        float mean = g_sum[c] * inv_n;
        float var  = g_sumsq[c] * inv_n - mean * mean;
        g_mean[c] = mean;
        g_rstd[c] = rsqrtf(var + BN_EPS);
    }
}

__global__ void bn_apply(const float* __restrict__ x, const float* __restrict__ bn_w,
                         const float* __restrict__ bn_b, const float* __restrict__ gamma,
                         float* __restrict__ out) {
    const size_t i4 = (size_t)blockIdx.x*blockDim.x + threadIdx.x;
    const size_t n4 = (size_t)BB*CC*LL/4;
    if (i4 >= n4) return;
    const int c = (int)((i4 / (LL/4)) % CC);
    const float w = bn_w[c]*g_rstd[c];
    const float bc = bn_b[c] - g_mean[c]*w;
    const float g = gamma[0];
    float4 v = ((const float4*)g_proj)[i4];
    float4 xr = ((const float4*)x)[i4];
    float4 y;
    y.x = g*(v.x*w + bc) + xr.x; y.y = g*(v.y*w + bc) + xr.y;
    y.z = g*(v.z*w + bc) + xr.z; y.w = g*(v.w*w + bc) + xr.w;
    y.x = y.x >= 0.f ? y.x : NEG_SLOPE*y.x; y.y = y.y >= 0.f ? y.y : NEG_SLOPE*y.y;
    y.z = y.z >= 0.f ? y.z : NEG_SLOPE*y.z; y.w = y.w >= 0.f ? y.w : NEG_SLOPE*y.w;
    ((float4*)out)[i4] = y;
}

// ------------------------- launch -------------------------
extern "C" void kernel_launch(void* const* d_in, const int* in_sizes, int n_in,
                              void* d_out, int out_size) {
    const float* x     = (const float*)d_in[0];
    const float* Wq    = (const float*)d_in[1];
    const float* Wk    = (const float*)d_in[2];
    const float* Wv    = (const float*)d_in[3];
    const float* Wo    = (const float*)d_in[4];
    const float* bn_w  = (const float*)d_in[5];
    const float* bn_b  = (const float*)d_in[6];
    const float* gamma = (const float*)d_in[7];
    float* out = (float*)d_out;

    __half *xt, *wqkv, *wo16, *ob;
    cudaGetSymbolAddress((void**)&xt,   g_xt);
    cudaGetSymbolAddress((void**)&wqkv, g_wqkv);
    cudaGetSymbolAddress((void**)&wo16, g_wo16);
    cudaGetSymbolAddress((void**)&ob,   g_ob);

    static bool once = false;
    if (!once) {
        cudaFuncSetAttribute(attn_mma, cudaFuncAttributeMaxDynamicSharedMemorySize, ATTN_SMEM);
        once = true;
    }

    cvt_all<<<512, 256>>>(Wq, Wk, Wv, Wo);
    zero_sums<<<1, 256>>>();
    xpose<<<dim3(LL/32, CC/32, BB), dim3(32,8)>>>(x);

    gemm_mma<256,0><<<dim3(12, (BB*LL)/128), 256>>>(xt, wqkv);
    attn_mma<<<dim3(LL/QT, BHT), 256, ATTN_SMEM>>>();
    gemm_mma<512,1><<<dim3(2, (BB*LL)/128), 256>>>(ob, wo16);

    bn_finalize<<<1, 256>>>();
    const int n4 = BB*CC*LL/4;
    bn_apply<<<(n4+255)/256, 256>>>(x, bn_w, bn_b, gamma, out);
}